// round 3
// baseline (speedup 1.0000x reference)
#include <cuda_runtime.h>
#include <math.h>

#define N_AUTH  50000
#define N_PAP   100000
#define N_TOT   150000
#define DD      128
#define NLAY    3
#define NEDGE   2400000
#define NEG_SLOPE 0.01f
#define EPSN    1e-12f

// ---------------- static device scratch (no runtime alloc allowed) ----------
static __device__ float g_ego [N_TOT * DD];      // current ego embeddings
static __device__ float g_side[N_TOT * DD];      // SpMM result
static __device__ float g_Wt  [NLAY * 2 * DD * DD]; // transposed weights, k-major
static __device__ int   g_rowptr[N_TOT + 1];
static __device__ int   g_wptr  [N_TOT];
static __device__ int   g_cnt   [N_TOT];
static __device__ int   g_colv  [NEDGE];
static __device__ float g_valv  [NEDGE];

// ---------------- small helpers --------------------------------------------
__device__ __forceinline__ unsigned long long pack2f(float x) {
    unsigned int u = __float_as_uint(x);
    unsigned long long r;
    asm("mov.b64 %0, {%1, %1};" : "=l"(r) : "r"(u));
    return r;
}
__device__ __forceinline__ void fma2(unsigned long long& d,
                                     unsigned long long a,
                                     unsigned long long b) {
    asm("fma.rn.f32x2 %0, %1, %2, %0;" : "+l"(d) : "l"(a), "l"(b));
}
union U64F2 { unsigned long long u; float2 f; };

// ---------------- CSR build -------------------------------------------------
__global__ void zero_cnt_kernel() {
    int i = blockIdx.x * blockDim.x + threadIdx.x;
    if (i < N_TOT) g_cnt[i] = 0;
}

__global__ void count_kernel(const int* __restrict__ rows) {
    int i = blockIdx.x * blockDim.x + threadIdx.x;
    if (i < NEDGE) atomicAdd(&g_cnt[rows[i]], 1);
}

// single-block exclusive scan over 150000 counts
__global__ void scan_kernel() {
    __shared__ int ssum[1024];
    const int t = threadIdx.x;
    const int CH = (N_TOT + 1023) / 1024;   // 147
    int start = t * CH;
    int end   = min(start + CH, N_TOT);
    int local = 0;
    for (int i = start; i < end; i++) local += g_cnt[i];
    ssum[t] = local;
    __syncthreads();
    for (int off = 1; off < 1024; off <<= 1) {
        int v = (t >= off) ? ssum[t - off] : 0;
        __syncthreads();
        ssum[t] += v;
        __syncthreads();
    }
    int run = ssum[t] - local;              // exclusive prefix
    for (int i = start; i < end; i++) {
        g_rowptr[i] = run;
        g_wptr[i]   = run;
        run += g_cnt[i];
    }
    if (t == 1023) g_rowptr[N_TOT] = ssum[1023];
}

__global__ void fill_kernel(const int* __restrict__ rows,
                            const int* __restrict__ cols,
                            const float* __restrict__ vals) {
    int i = blockIdx.x * blockDim.x + threadIdx.x;
    if (i < NEDGE) {
        int r = rows[i];
        int p = atomicAdd(&g_wptr[r], 1);
        g_colv[p] = cols[i];
        g_valv[p] = vals[i];
    }
}

// ---------------- init: ego = concat(author, paper); out layer 0 = raw ego --
__global__ void init_kernel(const float* __restrict__ author,
                            const float* __restrict__ paper,
                            float* __restrict__ out) {
    int i = blockIdx.x * blockDim.x + threadIdx.x;   // N_TOT * 32 float4 slots
    if (i >= N_TOT * 32) return;
    int node = i >> 5;
    int c4   = (i & 31) * 4;
    float4 v;
    if (node < N_AUTH) v = *reinterpret_cast<const float4*>(author + node * DD + c4);
    else               v = *reinterpret_cast<const float4*>(paper + (node - N_AUTH) * DD + c4);
    *reinterpret_cast<float4*>(g_ego + node * DD + c4) = v;
    *reinterpret_cast<float4*>(out + (size_t)node * (4 * DD) + c4) = v;
}

// ---------------- weight transpose: g_Wt[l][m][d][j] = W[l][j][d] -----------
__global__ void transpose_w_kernel(const float* __restrict__ W1,
                                   const float* __restrict__ W2) {
    int idx = blockIdx.x * blockDim.x + threadIdx.x;
    if (idx >= NLAY * 2 * DD * DD) return;
    int l   = idx / (2 * DD * DD);
    int rem = idx % (2 * DD * DD);
    int mat = rem / (DD * DD);
    int r2  = rem % (DD * DD);
    int d   = r2 / DD;
    int j   = r2 % DD;
    const float* src = (mat == 0) ? W1 : W2;
    g_Wt[idx] = src[l * DD * DD + j * DD + d];
}

// ---------------- SpMM: warp per row, 4 dims per lane -----------------------
__global__ void spmm_kernel() {
    int gt   = blockIdx.x * blockDim.x + threadIdx.x;
    int row  = gt >> 5;
    int lane = gt & 31;
    if (row >= N_TOT) return;
    int s = g_rowptr[row];
    int e = g_rowptr[row + 1];
    float4 a0 = make_float4(0.f, 0.f, 0.f, 0.f);
    float4 a1 = make_float4(0.f, 0.f, 0.f, 0.f);
    int i = s;
    for (; i + 1 < e; i += 2) {
        int   c0 = g_colv[i];
        float v0 = g_valv[i];
        int   c1 = g_colv[i + 1];
        float v1 = g_valv[i + 1];
        float4 x0 = *reinterpret_cast<const float4*>(g_ego + c0 * DD + lane * 4);
        float4 x1 = *reinterpret_cast<const float4*>(g_ego + c1 * DD + lane * 4);
        a0.x += v0 * x0.x; a0.y += v0 * x0.y; a0.z += v0 * x0.z; a0.w += v0 * x0.w;
        a1.x += v1 * x1.x; a1.y += v1 * x1.y; a1.z += v1 * x1.z; a1.w += v1 * x1.w;
    }
    if (i < e) {
        int   c0 = g_colv[i];
        float v0 = g_valv[i];
        float4 x0 = *reinterpret_cast<const float4*>(g_ego + c0 * DD + lane * 4);
        a0.x += v0 * x0.x; a0.y += v0 * x0.y; a0.z += v0 * x0.z; a0.w += v0 * x0.w;
    }
    a0.x += a1.x; a0.y += a1.y; a0.z += a1.z; a0.w += a1.w;
    *reinterpret_cast<float4*>(g_side + row * DD + lane * 4) = a0;
}

// ---------------- fused layer GEMM ------------------------------------------
// new_ego = leaky(side @ W1^T + b1) + leaky((ego*side) @ W2^T + b2)
// out[:, (l+1)*128 : (l+2)*128] = l2_normalize(new_ego);  g_ego = new_ego
//
// Block: 256 threads, 64 rows x 128 cols. Thread (cn = t&31, rm = t>>5)
// computes rows rm*8..rm*8+7, cols cn*4..cn*4+3 of BOTH branches (same j!).
#define BM 64
#define WP 132          // padded pitch (floats), keeps 16B alignment
#define GEMM_SMEM ((2 * DD * WP + 2 * BM * WP) * 4)

__global__ void __launch_bounds__(256, 1)
gemm_fused_kernel(const float* __restrict__ b1g,
                  const float* __restrict__ b2g,
                  float* __restrict__ out, int layer) {
    extern __shared__ float smem[];
    float* sW1 = smem;                    // [128][132]
    float* sW2 = sW1 + DD * WP;
    float* sS  = sW2 + DD * WP;           // [64][132]  side tile (row-major)
    float* sE  = sS  + BM * WP;           // [64][132]  ego*side tile

    const int t   = threadIdx.x;
    const int cn  = t & 31;
    const int rm  = t >> 5;
    const int cn4 = cn * 4;
    const int rm8 = rm * 8;
    const int base = blockIdx.x * BM;

    const float* Wt1 = g_Wt + (layer * 2    ) * DD * DD;
    const float* Wt2 = g_Wt + (layer * 2 + 1) * DD * DD;

    // load transposed weights (coalesced gmem, conflict-free smem)
    for (int i = t; i < DD * 32; i += 256) {
        int d = i >> 5, c = (i & 31) * 4;
        *reinterpret_cast<float4*>(&sW1[d * WP + c]) =
            *reinterpret_cast<const float4*>(Wt1 + d * DD + c);
        *reinterpret_cast<float4*>(&sW2[d * WP + c]) =
            *reinterpret_cast<const float4*>(Wt2 + d * DD + c);
    }
    // load A tiles: side and ego*side
    for (int i = t; i < BM * 32; i += 256) {
        int m = i >> 5, c = (i & 31) * 4;
        int row = base + m;
        float4 s4 = make_float4(0.f, 0.f, 0.f, 0.f);
        float4 e4 = make_float4(0.f, 0.f, 0.f, 0.f);
        if (row < N_TOT) {
            s4 = *reinterpret_cast<const float4*>(g_side + row * DD + c);
            e4 = *reinterpret_cast<const float4*>(g_ego  + row * DD + c);
        }
        float4 p4 = make_float4(s4.x * e4.x, s4.y * e4.y, s4.z * e4.z, s4.w * e4.w);
        *reinterpret_cast<float4*>(&sS[m * WP + c]) = s4;
        *reinterpret_cast<float4*>(&sE[m * WP + c]) = p4;
    }
    __syncthreads();

    unsigned long long acc1[8][2], acc2[8][2];
#pragma unroll
    for (int r = 0; r < 8; r++) {
        acc1[r][0] = 0ull; acc1[r][1] = 0ull;
        acc2[r][0] = 0ull; acc2[r][1] = 0ull;
    }

#pragma unroll 4
    for (int k = 0; k < DD; k++) {
        const ulonglong2 w1 = *reinterpret_cast<const ulonglong2*>(&sW1[k * WP + cn4]);
        const ulonglong2 w2 = *reinterpret_cast<const ulonglong2*>(&sW2[k * WP + cn4]);
#pragma unroll
        for (int r = 0; r < 8; r++) {
            float a1 = sS[(rm8 + r) * WP + k];   // broadcast across warp
            float a2 = sE[(rm8 + r) * WP + k];
            unsigned long long p1 = pack2f(a1);
            unsigned long long p2 = pack2f(a2);
            fma2(acc1[r][0], p1, w1.x);
            fma2(acc1[r][1], p1, w1.y);
            fma2(acc2[r][0], p2, w2.x);
            fma2(acc2[r][1], p2, w2.y);
        }
    }

    // epilogue: bias, leaky, add, row sumsq
    float bb1[4], bb2[4];
    {
        float4 b1v = *reinterpret_cast<const float4*>(b1g + layer * DD + cn4);
        float4 b2v = *reinterpret_cast<const float4*>(b2g + layer * DD + cn4);
        bb1[0] = b1v.x; bb1[1] = b1v.y; bb1[2] = b1v.z; bb1[3] = b1v.w;
        bb2[0] = b2v.x; bb2[1] = b2v.y; bb2[2] = b2v.z; bb2[3] = b2v.w;
    }

    float oo[8][4];
    float ss[8];
#pragma unroll
    for (int r = 0; r < 8; r++) {
        U64F2 c10, c11, c20, c21;
        c10.u = acc1[r][0]; c11.u = acc1[r][1];
        c20.u = acc2[r][0]; c21.u = acc2[r][1];
        float v1[4] = { c10.f.x, c10.f.y, c11.f.x, c11.f.y };
        float v2[4] = { c20.f.x, c20.f.y, c21.f.x, c21.f.y };
        float s = 0.f;
#pragma unroll
        for (int u = 0; u < 4; u++) {
            float x1 = v1[u] + bb1[u];
            x1 = (x1 >= 0.f) ? x1 : NEG_SLOPE * x1;
            float x2 = v2[u] + bb2[u];
            x2 = (x2 >= 0.f) ? x2 : NEG_SLOPE * x2;
            float ov = x1 + x2;
            oo[r][u] = ov;
            s += ov * ov;
        }
        ss[r] = s;
    }
    // warp all-reduce of row sumsq (row spread across the 32 lanes of this warp)
#pragma unroll
    for (int off = 16; off > 0; off >>= 1) {
#pragma unroll
        for (int r = 0; r < 8; r++)
            ss[r] += __shfl_xor_sync(0xffffffffu, ss[r], off);
    }

#pragma unroll
    for (int r = 0; r < 8; r++) {
        int row = base + rm8 + r;
        if (row < N_TOT) {
            float4 ov = make_float4(oo[r][0], oo[r][1], oo[r][2], oo[r][3]);
            *reinterpret_cast<float4*>(g_ego + row * DD + cn4) = ov;
            float nrm = sqrtf(ss[r]);
            float sc  = 1.0f / fmaxf(nrm, EPSN);
            float4 on = make_float4(ov.x * sc, ov.y * sc, ov.z * sc, ov.w * sc);
            *reinterpret_cast<float4*>(out + (size_t)row * (4 * DD)
                                       + (layer + 1) * DD + cn4) = on;
        }
    }
}

// ---------------- launch ----------------------------------------------------
extern "C" void kernel_launch(void* const* d_in, const int* in_sizes, int n_in,
                              void* d_out, int out_size) {
    const float* author = (const float*)d_in[0];
    const float* paper  = (const float*)d_in[1];
    const int*   rows   = (const int*)  d_in[2];
    const int*   cols   = (const int*)  d_in[3];
    const float* vals   = (const float*)d_in[4];
    const float* W1     = (const float*)d_in[5];
    const float* b1     = (const float*)d_in[6];
    const float* W2     = (const float*)d_in[7];
    const float* b2     = (const float*)d_in[8];
    float* out = (float*)d_out;

    cudaFuncSetAttribute(gemm_fused_kernel,
                         cudaFuncAttributeMaxDynamicSharedMemorySize, GEMM_SMEM);

    // CSR build (once per launch, reused by all 3 layers)
    transpose_w_kernel<<<(NLAY * 2 * DD * DD + 255) / 256, 256>>>(W1, W2);
    zero_cnt_kernel<<<(N_TOT + 255) / 256, 256>>>();
    count_kernel<<<(NEDGE + 255) / 256, 256>>>(rows);
    scan_kernel<<<1, 1024>>>();
    fill_kernel<<<(NEDGE + 255) / 256, 256>>>(rows, cols, vals);
    init_kernel<<<(N_TOT * 32 + 255) / 256, 256>>>(author, paper, out);

    const int gemm_blocks = (N_TOT + BM - 1) / BM;   // 2344
    const int spmm_threads = N_TOT * 32;
    for (int l = 0; l < NLAY; l++) {
        spmm_kernel<<<(spmm_threads + 255) / 256, 256>>>();
        gemm_fused_kernel<<<gemm_blocks, 256, GEMM_SMEM>>>(b1, b2, out, l);
    }
}

// round 5
// speedup vs baseline: 1.1649x; 1.1649x over previous
#include <cuda_runtime.h>
#include <math.h>

#define N_AUTH  50000
#define N_PAP   100000
#define N_TOT   150000
#define DD      128
#define NLAY    3
#define NEDGE   2400000
#define NEG_SLOPE 0.01f
#define EPSN    1e-12f

#define NBS     293          // scan blocks: ceil(150000/512)
#define SCH     512          // counts per scan block

// ---------------- static device scratch (no runtime alloc allowed) ----------
static __device__ float g_ego [N_TOT * DD];
static __device__ float g_side[N_TOT * DD];
static __device__ int   g_rowptr[N_TOT + 1];
static __device__ int   g_wptr  [N_TOT];
static __device__ int   g_cnt   [N_TOT];
static __device__ int   g_bsum  [NBS];
static __device__ int   g_colv  [NEDGE];
static __device__ float g_valv  [NEDGE];

// ---------------- helpers ----------------------------------------------------
__device__ __forceinline__ void fma2(unsigned long long& d,
                                     unsigned long long a,
                                     unsigned long long b) {
    asm("fma.rn.f32x2 %0, %1, %2, %0;" : "+l"(d) : "l"(a), "l"(b));
}
union U64F2 { unsigned long long u; float2 f; };

// ---------------- CSR build --------------------------------------------------
__global__ void zero_cnt_kernel() {
    int i = blockIdx.x * blockDim.x + threadIdx.x;
    if (i < N_TOT) g_cnt[i] = 0;
}

__global__ void count_kernel(const int* __restrict__ rows) {
    int i = blockIdx.x * blockDim.x + threadIdx.x;
    if (i < NEDGE) atomicAdd(&g_cnt[rows[i]], 1);
}

// scan stage 1: per-block sums of 512 counts
__global__ void scan1_kernel() {
    __shared__ int red[256];
    int b = blockIdx.x, t = threadIdx.x;
    int i0 = b * SCH + 2 * t;
    int v = 0;
    if (i0     < N_TOT) v += g_cnt[i0];
    if (i0 + 1 < N_TOT) v += g_cnt[i0 + 1];
    red[t] = v;
    __syncthreads();
    for (int o = 128; o > 0; o >>= 1) {
        if (t < o) red[t] += red[t + o];
        __syncthreads();
    }
    if (t == 0) g_bsum[b] = red[0];
}

// scan stage 2: 1 block scans the 293 block sums (exclusive)
__global__ void scan2_kernel() {
    __shared__ int s[512];
    int t = threadIdx.x;
    int v = (t < NBS) ? g_bsum[t] : 0;
    s[t] = v;
    __syncthreads();
    for (int o = 1; o < 512; o <<= 1) {
        int x = (t >= o) ? s[t - o] : 0;
        __syncthreads();
        s[t] += x;
        __syncthreads();
    }
    if (t < NBS) g_bsum[t] = s[t] - v;          // exclusive
    if (t == NBS - 1) g_rowptr[N_TOT] = s[t];   // grand total
}

// scan stage 3: local exclusive scan + block offset -> rowptr/wptr
__global__ void scan3_kernel() {
    __shared__ int sh[256];
    int b = blockIdx.x, t = threadIdx.x;
    int i0 = b * SCH + 2 * t;
    int c0 = (i0     < N_TOT) ? g_cnt[i0]     : 0;
    int c1 = (i0 + 1 < N_TOT) ? g_cnt[i0 + 1] : 0;
    int pair = c0 + c1;
    sh[t] = pair;
    __syncthreads();
    for (int o = 1; o < 256; o <<= 1) {
        int x = (t >= o) ? sh[t - o] : 0;
        __syncthreads();
        sh[t] += x;
        __syncthreads();
    }
    int excl = sh[t] - pair + g_bsum[b];
    if (i0 < N_TOT)     { g_rowptr[i0]     = excl;      g_wptr[i0]     = excl; }
    if (i0 + 1 < N_TOT) { g_rowptr[i0 + 1] = excl + c0; g_wptr[i0 + 1] = excl + c0; }
}

__global__ void fill_kernel(const int* __restrict__ rows,
                            const int* __restrict__ cols,
                            const float* __restrict__ vals) {
    int i = blockIdx.x * blockDim.x + threadIdx.x;
    if (i < NEDGE) {
        int r = rows[i];
        int p = atomicAdd(&g_wptr[r], 1);
        g_colv[p] = cols[i];
        g_valv[p] = vals[i];
    }
}

// ---------------- init: ego = concat(author, paper); out layer 0 = raw ego ---
__global__ void init_kernel(const float* __restrict__ author,
                            const float* __restrict__ paper,
                            float* __restrict__ out) {
    int i = blockIdx.x * blockDim.x + threadIdx.x;
    if (i >= N_TOT * 32) return;
    int node = i >> 5;
    int c4   = (i & 31) * 4;
    float4 v;
    if (node < N_AUTH) v = *reinterpret_cast<const float4*>(author + node * DD + c4);
    else               v = *reinterpret_cast<const float4*>(paper + (node - N_AUTH) * DD + c4);
    *reinterpret_cast<float4*>(g_ego + node * DD + c4) = v;
    *reinterpret_cast<float4*>(out + (size_t)node * (4 * DD) + c4) = v;
}

// ---------------- SpMM: warp per row, 4 dims per lane ------------------------
__global__ void spmm_kernel() {
    int gt   = blockIdx.x * blockDim.x + threadIdx.x;
    int row  = gt >> 5;
    int lane = gt & 31;
    if (row >= N_TOT) return;
    int s = g_rowptr[row];
    int e = g_rowptr[row + 1];
    float4 a0 = make_float4(0.f, 0.f, 0.f, 0.f);
    float4 a1 = make_float4(0.f, 0.f, 0.f, 0.f);
    int i = s;
    for (; i + 1 < e; i += 2) {
        int   c0 = g_colv[i];
        float v0 = g_valv[i];
        int   c1 = g_colv[i + 1];
        float v1 = g_valv[i + 1];
        float4 x0 = *reinterpret_cast<const float4*>(g_ego + c0 * DD + lane * 4);
        float4 x1 = *reinterpret_cast<const float4*>(g_ego + c1 * DD + lane * 4);
        a0.x += v0 * x0.x; a0.y += v0 * x0.y; a0.z += v0 * x0.z; a0.w += v0 * x0.w;
        a1.x += v1 * x1.x; a1.y += v1 * x1.y; a1.z += v1 * x1.z; a1.w += v1 * x1.w;
    }
    if (i < e) {
        int   c0 = g_colv[i];
        float v0 = g_valv[i];
        float4 x0 = *reinterpret_cast<const float4*>(g_ego + c0 * DD + lane * 4);
        a0.x += v0 * x0.x; a0.y += v0 * x0.y; a0.z += v0 * x0.z; a0.w += v0 * x0.w;
    }
    a0.x += a1.x; a0.y += a1.y; a0.z += a1.z; a0.w += a1.w;
    *reinterpret_cast<float4*>(g_side + row * DD + lane * 4) = a0;
}

// ---------------- fused layer GEMM -------------------------------------------
// new_ego = leaky(side @ W1^T + b1) + leaky((ego*side) @ W2^T + b2)
// out[:, (l+1)*128:(l+2)*128] = l2_normalize(new_ego);  g_ego = new_ego
//
// Split-K paired accumulators: each u64 acc = (even-k partial, odd-k partial).
// A tiles row-major in smem -> (a[k],a[k+1]) is a contiguous u64.
// W j-major (original layout) in smem -> (W[j][k],W[j][k+1]) contiguous u64.
// Zero packing movs in the inner loop.
//
// Block: 512 threads, 64 rows x 128 cols.
//   rg = t>>6 (0..7): rows rg*8..rg*8+7
//   cn = t&63 (0..63): cols cn and cn+64
#define BM 64
#define PW 132       // pitch in floats: keeps 16B alignment, bank-stride 4
#define GEMM_SMEM ((2 * DD * PW + 2 * BM * PW) * 4)

__global__ void __launch_bounds__(512, 1)
gemm_fused_kernel(const float* __restrict__ W1g,
                  const float* __restrict__ W2g,
                  const float* __restrict__ b1g,
                  const float* __restrict__ b2g,
                  float* __restrict__ out, int layer) {
    extern __shared__ float smem[];
    float* sW1 = smem;                    // [128 j][PW] j-major
    float* sW2 = sW1 + DD * PW;
    float* sS  = sW2 + DD * PW;           // [64 m][PW] row-major (side)
    float* sE  = sS  + BM * PW;           // [64 m][PW] row-major (ego*side)

    const int t    = threadIdx.x;
    const int cn   = t & 63;
    const int rg   = t >> 6;
    const int base = blockIdx.x * BM;

    const float* W1 = W1g + layer * DD * DD;
    const float* W2 = W2g + layer * DD * DD;

    // load W (j-major, straight copy)
    for (int i = t; i < DD * 32; i += 512) {
        int j = i >> 5, c = (i & 31) * 4;
        *reinterpret_cast<float4*>(&sW1[j * PW + c]) =
            *reinterpret_cast<const float4*>(W1 + j * DD + c);
        *reinterpret_cast<float4*>(&sW2[j * PW + c]) =
            *reinterpret_cast<const float4*>(W2 + j * DD + c);
    }
    // load A tiles: side and ego*side
    for (int i = t; i < BM * 32; i += 512) {
        int m = i >> 5, c = (i & 31) * 4;
        int row = base + m;
        float4 s4 = make_float4(0.f, 0.f, 0.f, 0.f);
        float4 e4 = make_float4(0.f, 0.f, 0.f, 0.f);
        if (row < N_TOT) {
            s4 = *reinterpret_cast<const float4*>(g_side + row * DD + c);
            e4 = *reinterpret_cast<const float4*>(g_ego  + row * DD + c);
        }
        float4 p4 = make_float4(s4.x * e4.x, s4.y * e4.y, s4.z * e4.z, s4.w * e4.w);
        *reinterpret_cast<float4*>(&sS[m * PW + c]) = s4;
        *reinterpret_cast<float4*>(&sE[m * PW + c]) = p4;
    }
    __syncthreads();

    unsigned long long acc1[8][2], acc2[8][2];   // [row][col u]: u64=(even,odd) K partials
#pragma unroll
    for (int r = 0; r < 8; r++) {
        acc1[r][0] = 0ull; acc1[r][1] = 0ull;
        acc2[r][0] = 0ull; acc2[r][1] = 0ull;
    }

    const float* pS   = &sS[(rg * 8) * PW];
    const float* pE   = &sE[(rg * 8) * PW];
    const float* pW1a = &sW1[cn * PW];
    const float* pW1b = &sW1[(cn + 64) * PW];
    const float* pW2a = &sW2[cn * PW];
    const float* pW2b = &sW2[(cn + 64) * PW];

#pragma unroll 2
    for (int k = 0; k < DD; k += 4) {
        ulonglong2 w1a = *reinterpret_cast<const ulonglong2*>(pW1a + k);
        ulonglong2 w1b = *reinterpret_cast<const ulonglong2*>(pW1b + k);
        ulonglong2 w2a = *reinterpret_cast<const ulonglong2*>(pW2a + k);
        ulonglong2 w2b = *reinterpret_cast<const ulonglong2*>(pW2b + k);
#pragma unroll
        for (int r = 0; r < 8; r++) {
            ulonglong2 aS = *reinterpret_cast<const ulonglong2*>(pS + r * PW + k);
            ulonglong2 aE = *reinterpret_cast<const ulonglong2*>(pE + r * PW + k);
            fma2(acc1[r][0], aS.x, w1a.x); fma2(acc1[r][0], aS.y, w1a.y);
            fma2(acc1[r][1], aS.x, w1b.x); fma2(acc1[r][1], aS.y, w1b.y);
            fma2(acc2[r][0], aE.x, w2a.x); fma2(acc2[r][0], aE.y, w2a.y);
            fma2(acc2[r][1], aE.x, w2b.x); fma2(acc2[r][1], aE.y, w2b.y);
        }
    }

    // epilogue: combine split-K halves, bias, leaky, add, row sumsq
    const float bb1a = b1g[layer * DD + cn];
    const float bb1b = b1g[layer * DD + cn + 64];
    const float bb2a = b2g[layer * DD + cn];
    const float bb2b = b2g[layer * DD + cn + 64];

    float oo[8][2];
    float ss[8];
#pragma unroll
    for (int r = 0; r < 8; r++) {
        U64F2 x;
        x.u = acc1[r][0]; float v1a = x.f.x + x.f.y;
        x.u = acc1[r][1]; float v1b = x.f.x + x.f.y;
        x.u = acc2[r][0]; float v2a = x.f.x + x.f.y;
        x.u = acc2[r][1]; float v2b = x.f.x + x.f.y;
        float x1 = v1a + bb1a; x1 = (x1 >= 0.f) ? x1 : NEG_SLOPE * x1;
        float x2 = v2a + bb2a; x2 = (x2 >= 0.f) ? x2 : NEG_SLOPE * x2;
        float y1 = v1b + bb1b; y1 = (y1 >= 0.f) ? y1 : NEG_SLOPE * y1;
        float y2 = v2b + bb2b; y2 = (y2 >= 0.f) ? y2 : NEG_SLOPE * y2;
        float o0 = x1 + x2;
        float o1 = y1 + y2;
        oo[r][0] = o0; oo[r][1] = o1;
        ss[r] = o0 * o0 + o1 * o1;
    }
    // intra-warp reduce (each warp covers 32 of the 64 column-threads)
#pragma unroll
    for (int off = 16; off > 0; off >>= 1) {
#pragma unroll
        for (int r = 0; r < 8; r++)
            ss[r] += __shfl_xor_sync(0xffffffffu, ss[r], off);
    }
    // combine the two warps of each row-group via smem (reuse sS)
    __syncthreads();
    float* sRed = sS;                      // [16 warps][8 rows]
    const int wid  = t >> 5;
    const int lane = t & 31;
    if (lane == 0) {
#pragma unroll
        for (int r = 0; r < 8; r++) sRed[wid * 8 + r] = ss[r];
    }
    __syncthreads();

#pragma unroll
    for (int r = 0; r < 8; r++) {
        float tot = sRed[(2 * rg) * 8 + r] + sRed[(2 * rg + 1) * 8 + r];
        int row = base + rg * 8 + r;
        if (row < N_TOT) {
            float sc = 1.0f / fmaxf(sqrtf(tot), EPSN);
            g_ego[row * DD + cn]      = oo[r][0];
            g_ego[row * DD + cn + 64] = oo[r][1];
            size_t ob = (size_t)row * (4 * DD) + (size_t)(layer + 1) * DD;
            out[ob + cn]      = oo[r][0] * sc;
            out[ob + cn + 64] = oo[r][1] * sc;
        }
    }
}

// ---------------- launch -----------------------------------------------------
extern "C" void kernel_launch(void* const* d_in, const int* in_sizes, int n_in,
                              void* d_out, int out_size) {
    const float* author = (const float*)d_in[0];
    const float* paper  = (const float*)d_in[1];
    const int*   rows   = (const int*)  d_in[2];
    const int*   cols   = (const int*)  d_in[3];
    const float* vals   = (const float*)d_in[4];
    const float* W1     = (const float*)d_in[5];
    const float* b1     = (const float*)d_in[6];
    const float* W2     = (const float*)d_in[7];
    const float* b2     = (const float*)d_in[8];
    float* out = (float*)d_out;

    cudaFuncSetAttribute(gemm_fused_kernel,
                         cudaFuncAttributeMaxDynamicSharedMemorySize, GEMM_SMEM);

    // CSR build (once per launch, reused by all 3 layers)
    zero_cnt_kernel<<<(N_TOT + 255) / 256, 256>>>();
    count_kernel<<<(NEDGE + 255) / 256, 256>>>(rows);
    scan1_kernel<<<NBS, 256>>>();
    scan2_kernel<<<1, 512>>>();
    scan3_kernel<<<NBS, 256>>>();
    fill_kernel<<<(NEDGE + 255) / 256, 256>>>(rows, cols, vals);
    init_kernel<<<(N_TOT * 32 + 255) / 256, 256>>>(author, paper, out);

    const int gemm_blocks  = (N_TOT + BM - 1) / BM;   // 2344
    const int spmm_threads = N_TOT * 32;
    for (int l = 0; l < NLAY; l++) {
        spmm_kernel<<<(spmm_threads + 255) / 256, 256>>>();
        gemm_fused_kernel<<<gemm_blocks, 512, GEMM_SMEM>>>(W1, W2, b1, b2, out, l);
    }
}

// round 6
// speedup vs baseline: 1.2510x; 1.0739x over previous
#include <cuda_runtime.h>
#include <math.h>

#define N_AUTH  50000
#define N_PAP   100000
#define N_TOT   150000
#define DD      128
#define NLAY    3
#define NEDGE   2400000
#define NEG_SLOPE 0.01f
#define EPSN    1e-12f

#define NBS     293          // scan blocks: ceil(150000/512)
#define SCH     512          // counts per scan block

// ---------------- static device scratch (no runtime alloc allowed) ----------
static __device__ float g_ego [N_TOT * DD];
static __device__ float g_side[N_TOT * DD];
static __device__ int   g_rowptr[N_TOT + 1];
static __device__ int   g_wptr  [N_TOT];
static __device__ int   g_cnt   [N_TOT];
static __device__ int   g_bsum  [NBS];
static __device__ int   g_colv  [NEDGE];
static __device__ float g_valv  [NEDGE];

// ---------------- helpers ----------------------------------------------------
__device__ __forceinline__ void fma2(unsigned long long& d,
                                     unsigned long long a,
                                     unsigned long long b) {
    asm("fma.rn.f32x2 %0, %1, %2, %0;" : "+l"(d) : "l"(a), "l"(b));
}
union U64F2 { unsigned long long u; float2 f; };

// ---------------- CSR build --------------------------------------------------
__global__ void zero_cnt_kernel() {
    int i = blockIdx.x * blockDim.x + threadIdx.x;
    if (i < N_TOT) g_cnt[i] = 0;
}

__global__ void count_kernel(const int* __restrict__ rows) {
    int i = blockIdx.x * blockDim.x + threadIdx.x;
    if (i < NEDGE) atomicAdd(&g_cnt[rows[i]], 1);
}

__global__ void scan1_kernel() {
    __shared__ int red[256];
    int b = blockIdx.x, t = threadIdx.x;
    int i0 = b * SCH + 2 * t;
    int v = 0;
    if (i0     < N_TOT) v += g_cnt[i0];
    if (i0 + 1 < N_TOT) v += g_cnt[i0 + 1];
    red[t] = v;
    __syncthreads();
    for (int o = 128; o > 0; o >>= 1) {
        if (t < o) red[t] += red[t + o];
        __syncthreads();
    }
    if (t == 0) g_bsum[b] = red[0];
}

__global__ void scan2_kernel() {
    __shared__ int s[512];
    int t = threadIdx.x;
    int v = (t < NBS) ? g_bsum[t] : 0;
    s[t] = v;
    __syncthreads();
    for (int o = 1; o < 512; o <<= 1) {
        int x = (t >= o) ? s[t - o] : 0;
        __syncthreads();
        s[t] += x;
        __syncthreads();
    }
    if (t < NBS) g_bsum[t] = s[t] - v;
    if (t == NBS - 1) g_rowptr[N_TOT] = s[t];
}

__global__ void scan3_kernel() {
    __shared__ int sh[256];
    int b = blockIdx.x, t = threadIdx.x;
    int i0 = b * SCH + 2 * t;
    int c0 = (i0     < N_TOT) ? g_cnt[i0]     : 0;
    int c1 = (i0 + 1 < N_TOT) ? g_cnt[i0 + 1] : 0;
    int pair = c0 + c1;
    sh[t] = pair;
    __syncthreads();
    for (int o = 1; o < 256; o <<= 1) {
        int x = (t >= o) ? sh[t - o] : 0;
        __syncthreads();
        sh[t] += x;
        __syncthreads();
    }
    int excl = sh[t] - pair + g_bsum[b];
    if (i0 < N_TOT)     { g_rowptr[i0]     = excl;      g_wptr[i0]     = excl; }
    if (i0 + 1 < N_TOT) { g_rowptr[i0 + 1] = excl + c0; g_wptr[i0 + 1] = excl + c0; }
}

__global__ void fill_kernel(const int* __restrict__ rows,
                            const int* __restrict__ cols,
                            const float* __restrict__ vals) {
    int i = blockIdx.x * blockDim.x + threadIdx.x;
    if (i < NEDGE) {
        int r = rows[i];
        int p = atomicAdd(&g_wptr[r], 1);
        g_colv[p] = cols[i];
        g_valv[p] = vals[i];
    }
}

// ---------------- init -------------------------------------------------------
__global__ void init_kernel(const float* __restrict__ author,
                            const float* __restrict__ paper,
                            float* __restrict__ out) {
    int i = blockIdx.x * blockDim.x + threadIdx.x;
    if (i >= N_TOT * 32) return;
    int node = i >> 5;
    int c4   = (i & 31) * 4;
    float4 v;
    if (node < N_AUTH) v = *reinterpret_cast<const float4*>(author + node * DD + c4);
    else               v = *reinterpret_cast<const float4*>(paper + (node - N_AUTH) * DD + c4);
    *reinterpret_cast<float4*>(g_ego + node * DD + c4) = v;
    *reinterpret_cast<float4*>(out + (size_t)node * (4 * DD) + c4) = v;
}

// ---------------- SpMM: warp per row, 4 dims per lane, unroll-4 --------------
__global__ void spmm_kernel() {
    int gt   = blockIdx.x * blockDim.x + threadIdx.x;
    int row  = gt >> 5;
    int lane = gt & 31;
    if (row >= N_TOT) return;
    int s = g_rowptr[row];
    int e = g_rowptr[row + 1];
    const float* egoL = g_ego + lane * 4;
    float4 a0 = make_float4(0.f, 0.f, 0.f, 0.f);
    float4 a1 = make_float4(0.f, 0.f, 0.f, 0.f);
    int i = s;
    for (; i + 3 < e; i += 4) {
        int   c0 = g_colv[i];
        int   c1 = g_colv[i + 1];
        int   c2 = g_colv[i + 2];
        int   c3 = g_colv[i + 3];
        float v0 = g_valv[i];
        float v1 = g_valv[i + 1];
        float v2 = g_valv[i + 2];
        float v3 = g_valv[i + 3];
        float4 x0 = *reinterpret_cast<const float4*>(egoL + c0 * DD);
        float4 x1 = *reinterpret_cast<const float4*>(egoL + c1 * DD);
        float4 x2 = *reinterpret_cast<const float4*>(egoL + c2 * DD);
        float4 x3 = *reinterpret_cast<const float4*>(egoL + c3 * DD);
        a0.x += v0 * x0.x; a0.y += v0 * x0.y; a0.z += v0 * x0.z; a0.w += v0 * x0.w;
        a1.x += v1 * x1.x; a1.y += v1 * x1.y; a1.z += v1 * x1.z; a1.w += v1 * x1.w;
        a0.x += v2 * x2.x; a0.y += v2 * x2.y; a0.z += v2 * x2.z; a0.w += v2 * x2.w;
        a1.x += v3 * x3.x; a1.y += v3 * x3.y; a1.z += v3 * x3.z; a1.w += v3 * x3.w;
    }
    for (; i < e; i++) {
        int   c0 = g_colv[i];
        float v0 = g_valv[i];
        float4 x0 = *reinterpret_cast<const float4*>(egoL + c0 * DD);
        a0.x += v0 * x0.x; a0.y += v0 * x0.y; a0.z += v0 * x0.z; a0.w += v0 * x0.w;
    }
    a0.x += a1.x; a0.y += a1.y; a0.z += a1.z; a0.w += a1.w;
    *reinterpret_cast<float4*>(g_side + row * DD + lane * 4) = a0;
}

// ---------------- persistent fused layer GEMM --------------------------------
// new_ego = leaky(side @ W1^T + b1) + leaky((ego*side) @ W2^T + b2)
// out[:, (l+1)*128:(l+2)*128] = l2_normalize(new_ego);  g_ego = new_ego
//
// grid = GRID_GEMM persistent blocks; W staged in smem ONCE per block;
// A tiles software-pipelined through registers (prefetch next during compute).
#define BM 64
#define PW 132
#define NTILES ((N_TOT + BM - 1) / BM)     // 2344
#define GRID_GEMM 148
#define GEMM_SMEM ((2 * DD * PW + 2 * BM * PW) * 4)

__global__ void __launch_bounds__(512, 1)
gemm_fused_kernel(const float* __restrict__ W1g,
                  const float* __restrict__ W2g,
                  const float* __restrict__ b1g,
                  const float* __restrict__ b2g,
                  float* __restrict__ out, int layer) {
    extern __shared__ float smem[];
    float* sW1 = smem;                    // [128 j][PW] j-major
    float* sW2 = sW1 + DD * PW;
    float* sS  = sW2 + DD * PW;           // [64 m][PW]
    float* sE  = sS  + BM * PW;
    __shared__ float sRed[16 * 8];        // cross-warp sumsq

    const int t   = threadIdx.x;
    const int cn  = t & 63;
    const int rg  = t >> 6;
    const int wid  = t >> 5;
    const int lane = t & 31;

    // ---- stage weights once ----
    {
        const float* W1 = W1g + layer * DD * DD;
        const float* W2 = W2g + layer * DD * DD;
        for (int i = t; i < DD * 32; i += 512) {
            int j = i >> 5, c = (i & 31) * 4;
            *reinterpret_cast<float4*>(&sW1[j * PW + c]) =
                *reinterpret_cast<const float4*>(W1 + j * DD + c);
            *reinterpret_cast<float4*>(&sW2[j * PW + c]) =
                *reinterpret_cast<const float4*>(W2 + j * DD + c);
        }
    }

    const float bb1a = b1g[layer * DD + cn];
    const float bb1b = b1g[layer * DD + cn + 64];
    const float bb2a = b2g[layer * DD + cn];
    const float bb2b = b2g[layer * DD + cn + 64];

    // per-thread A slots: column c fixed, rows m = (t>>5) + 16*rep
    const int am = t >> 5;                 // 0..15
    const int ac = (t & 31) * 4;           // 0..124

    const float* pS   = &sS[(rg * 8) * PW];
    const float* pE   = &sE[(rg * 8) * PW];
    const float* pW1a = &sW1[cn * PW];
    const float* pW1b = &sW1[(cn + 64) * PW];
    const float* pW2a = &sW2[cn * PW];
    const float* pW2b = &sW2[(cn + 64) * PW];

    float4 s4[4], e4[4];

    // prefetch first tile
    int tile = blockIdx.x;
    {
        int base = tile * BM;
#pragma unroll
        for (int rep = 0; rep < 4; rep++) {
            int row = base + am + 16 * rep;
            if (row < N_TOT) {
                s4[rep] = *reinterpret_cast<const float4*>(g_side + row * DD + ac);
                e4[rep] = *reinterpret_cast<const float4*>(g_ego  + row * DD + ac);
            } else {
                s4[rep] = make_float4(0.f, 0.f, 0.f, 0.f);
                e4[rep] = make_float4(0.f, 0.f, 0.f, 0.f);
            }
        }
    }

    while (tile < NTILES) {
        // ---- store staged tile to smem ----
        __syncthreads();                   // previous iteration done with sS/sE
#pragma unroll
        for (int rep = 0; rep < 4; rep++) {
            int m = am + 16 * rep;
            float4 sv = s4[rep], ev = e4[rep];
            float4 pv = make_float4(sv.x * ev.x, sv.y * ev.y, sv.z * ev.z, sv.w * ev.w);
            *reinterpret_cast<float4*>(&sS[m * PW + ac]) = sv;
            *reinterpret_cast<float4*>(&sE[m * PW + ac]) = pv;
        }
        __syncthreads();

        const int base = tile * BM;
        const int next = tile + GRID_GEMM;

        // ---- prefetch next tile (global loads overlap compute below) ----
        if (next < NTILES) {
            int nb = next * BM;
#pragma unroll
            for (int rep = 0; rep < 4; rep++) {
                int row = nb + am + 16 * rep;
                if (row < N_TOT) {
                    s4[rep] = *reinterpret_cast<const float4*>(g_side + row * DD + ac);
                    e4[rep] = *reinterpret_cast<const float4*>(g_ego  + row * DD + ac);
                } else {
                    s4[rep] = make_float4(0.f, 0.f, 0.f, 0.f);
                    e4[rep] = make_float4(0.f, 0.f, 0.f, 0.f);
                }
            }
        }

        // ---- compute: split-K paired accumulators ----
        unsigned long long acc1[8][2], acc2[8][2];
#pragma unroll
        for (int r = 0; r < 8; r++) {
            acc1[r][0] = 0ull; acc1[r][1] = 0ull;
            acc2[r][0] = 0ull; acc2[r][1] = 0ull;
        }

#pragma unroll 2
        for (int k = 0; k < DD; k += 4) {
            ulonglong2 w1a = *reinterpret_cast<const ulonglong2*>(pW1a + k);
            ulonglong2 w1b = *reinterpret_cast<const ulonglong2*>(pW1b + k);
            ulonglong2 w2a = *reinterpret_cast<const ulonglong2*>(pW2a + k);
            ulonglong2 w2b = *reinterpret_cast<const ulonglong2*>(pW2b + k);
#pragma unroll
            for (int r = 0; r < 8; r++) {
                ulonglong2 aS = *reinterpret_cast<const ulonglong2*>(pS + r * PW + k);
                ulonglong2 aE = *reinterpret_cast<const ulonglong2*>(pE + r * PW + k);
                fma2(acc1[r][0], aS.x, w1a.x); fma2(acc1[r][0], aS.y, w1a.y);
                fma2(acc1[r][1], aS.x, w1b.x); fma2(acc1[r][1], aS.y, w1b.y);
                fma2(acc2[r][0], aE.x, w2a.x); fma2(acc2[r][0], aE.y, w2a.y);
                fma2(acc2[r][1], aE.x, w2b.x); fma2(acc2[r][1], aE.y, w2b.y);
            }
        }

        // ---- epilogue ----
        float oo[8][2];
        float ss[8];
#pragma unroll
        for (int r = 0; r < 8; r++) {
            U64F2 x;
            x.u = acc1[r][0]; float v1a = x.f.x + x.f.y;
            x.u = acc1[r][1]; float v1b = x.f.x + x.f.y;
            x.u = acc2[r][0]; float v2a = x.f.x + x.f.y;
            x.u = acc2[r][1]; float v2b = x.f.x + x.f.y;
            float x1 = v1a + bb1a; x1 = (x1 >= 0.f) ? x1 : NEG_SLOPE * x1;
            float x2 = v2a + bb2a; x2 = (x2 >= 0.f) ? x2 : NEG_SLOPE * x2;
            float y1 = v1b + bb1b; y1 = (y1 >= 0.f) ? y1 : NEG_SLOPE * y1;
            float y2 = v2b + bb2b; y2 = (y2 >= 0.f) ? y2 : NEG_SLOPE * y2;
            float o0 = x1 + x2;
            float o1 = y1 + y2;
            oo[r][0] = o0; oo[r][1] = o1;
            ss[r] = o0 * o0 + o1 * o1;
        }
#pragma unroll
        for (int off = 16; off > 0; off >>= 1) {
#pragma unroll
            for (int r = 0; r < 8; r++)
                ss[r] += __shfl_xor_sync(0xffffffffu, ss[r], off);
        }
        __syncthreads();                   // sRed reuse barrier (also guards prev read)
        if (lane == 0) {
#pragma unroll
            for (int r = 0; r < 8; r++) sRed[wid * 8 + r] = ss[r];
        }
        __syncthreads();

#pragma unroll
        for (int r = 0; r < 8; r++) {
            float tot = sRed[(2 * rg) * 8 + r] + sRed[(2 * rg + 1) * 8 + r];
            int row = base + rg * 8 + r;
            if (row < N_TOT) {
                float sc = 1.0f / fmaxf(sqrtf(tot), EPSN);
                g_ego[row * DD + cn]      = oo[r][0];
                g_ego[row * DD + cn + 64] = oo[r][1];
                size_t ob = (size_t)row * (4 * DD) + (size_t)(layer + 1) * DD;
                out[ob + cn]      = oo[r][0] * sc;
                out[ob + cn + 64] = oo[r][1] * sc;
            }
        }

        tile = next;
    }
}

// ---------------- launch -----------------------------------------------------
extern "C" void kernel_launch(void* const* d_in, const int* in_sizes, int n_in,
                              void* d_out, int out_size) {
    const float* author = (const float*)d_in[0];
    const float* paper  = (const float*)d_in[1];
    const int*   rows   = (const int*)  d_in[2];
    const int*   cols   = (const int*)  d_in[3];
    const float* vals   = (const float*)d_in[4];
    const float* W1     = (const float*)d_in[5];
    const float* b1     = (const float*)d_in[6];
    const float* W2     = (const float*)d_in[7];
    const float* b2     = (const float*)d_in[8];
    float* out = (float*)d_out;

    cudaFuncSetAttribute(gemm_fused_kernel,
                         cudaFuncAttributeMaxDynamicSharedMemorySize, GEMM_SMEM);

    zero_cnt_kernel<<<(N_TOT + 255) / 256, 256>>>();
    count_kernel<<<(NEDGE + 255) / 256, 256>>>(rows);
    scan1_kernel<<<NBS, 256>>>();
    scan2_kernel<<<1, 512>>>();
    scan3_kernel<<<NBS, 256>>>();
    fill_kernel<<<(NEDGE + 255) / 256, 256>>>(rows, cols, vals);
    init_kernel<<<(N_TOT * 32 + 255) / 256, 256>>>(author, paper, out);

    const int spmm_threads = N_TOT * 32;
    for (int l = 0; l < NLAY; l++) {
        spmm_kernel<<<(spmm_threads + 255) / 256, 256>>>();
        gemm_fused_kernel<<<GRID_GEMM, 512, GEMM_SMEM>>>(W1, W2, b1, b2, out, l);
    }
}